// round 14
// baseline (speedup 1.0000x reference)
#include <cuda_runtime.h>
#include <math_constants.h>
#include <cstdint>

#define BB 8
#define CC 256
#define HH 128
#define WW 128
#define HW (HH*WW)
#define TOPK 10
#define THRESH 0.5f
#define MARGIN 0.5f
#define EPSV 1e-8f
#define NMAPS 16
#define NCTA 256                   // all co-resident: min 2 CTAs/SM => 296 slots
#define JCTAS 8
#define JROWS 16
#define JPIX (JROWS*WW)
#define PADW 130
#define STG_ROWS 18
#define NT 256
#define CAP 512                    // exact max strict-3x3 maxima in 16x128

// scratch (no allocations); all counters self-reset -> graph-replay-safe
__device__ float    g_intensity[NMAPS][HW];
__device__ float    g_part_val[NMAPS][JCTAS][TOPK];
__device__ int      g_part_idx[NMAPS][JCTAS][TOPK];
__device__ float    g_losses[BB];
__device__ unsigned g_samp_cnt[BB];
__device__ unsigned g_done_cnt;
__device__ unsigned g_bar_arrive;
__device__ unsigned g_bar_depart;

__device__ __forceinline__ unsigned redux_max_u32(unsigned v) {
    unsigned r;
    asm volatile("redux.sync.max.u32 %0, %1, 0xffffffff;" : "=r"(r) : "r"(v));
    return r;
}
__device__ __forceinline__ unsigned redux_min_u32(unsigned v) {
    unsigned r;
    asm volatile("redux.sync.min.u32 %0, %1, 0xffffffff;" : "=r"(r) : "r"(v));
    return r;
}

__global__ void __launch_bounds__(NT, 2) fused_kernel(
    const float* __restrict__ det, const float* __restrict__ loc,
    float* __restrict__ out)
{
    __shared__ float sbuf[5120];                  // 20KB phase-union
    float4* s_part = (float4*)sbuf;               // stream: 256 float4
    float*  rawp   = sbuf;                        // region: 18*130 = 2340
    float*  s_cval = sbuf + 2560;                 // region: CAP
    int*    s_cidx = (int*)(sbuf + 2560 + CAP);   // region: CAP
    float (*df)[CC] = (float(*)[CC])sbuf;         // loss alias
    float (*lf)[CC] = (float(*)[CC])(sbuf + 2560);

    __shared__ float s_mv[2][JCTAS * TOPK];
    __shared__ int   s_mi[2][JCTAS * TOPK];
    __shared__ float s_dkv[TOPK], s_lkv[TOPK];
    __shared__ int   s_dki[TOPK], s_lki[TOPK];
    __shared__ float s_na[TOPK], s_nb[TOPK], s_ws[8];
    __shared__ int   s_cn;
    __shared__ unsigned s_flag;

    const int tid  = threadIdx.x;
    const int lane = tid & 31;
    const int w    = tid >> 5;
    const int bid  = blockIdx.x;                  // 0..255

    // ============ Phase A: intensity stream (R10 layout, R11 reg headroom) ==
    {
        const int sm   = bid >> 4;                // map 0..15
        const int sl   = bid & 15;                // slice
        const int sb   = sm & 7;
        const int half = tid >> 7;                // channel half
        const int gl   = tid & 127;
        const int g0   = sl * 256 + gl;           // groups g0, g0+128
        const float* src = (sm < 8) ? det : loc;
        const float4* base = ((const float4*)(src + (size_t)sb * CC * HW))
                             + (size_t)half * 128 * (HW / 4);
        const float4* p0 = base + g0;
        const float4* p1 = base + g0 + 128;

        float a0=0.f,a1=0.f,a2=0.f,a3=0.f, b0=0.f,b1=0.f,b2=0.f,b3=0.f;
        #pragma unroll 1
        for (int c0 = 0; c0 < 128; c0 += 4) {
            float4 v[8];
            #pragma unroll
            for (int i = 0; i < 4; i++) {
                v[i]     = __ldcs(p0 + (size_t)(c0 + i) * (HW / 4));
                v[4 + i] = __ldcs(p1 + (size_t)(c0 + i) * (HW / 4));
            }
            #pragma unroll
            for (int i = 0; i < 4; i++) {
                a0 = fmaf(v[i].x, v[i].x, a0);
                a1 = fmaf(v[i].y, v[i].y, a1);
                a2 = fmaf(v[i].z, v[i].z, a2);
                a3 = fmaf(v[i].w, v[i].w, a3);
                b0 = fmaf(v[4+i].x, v[4+i].x, b0);
                b1 = fmaf(v[4+i].y, v[4+i].y, b1);
                b2 = fmaf(v[4+i].z, v[4+i].z, b2);
                b3 = fmaf(v[4+i].w, v[4+i].w, b3);
            }
        }
        if (half) {
            s_part[gl]       = make_float4(a0, a1, a2, a3);
            s_part[gl + 128] = make_float4(b0, b1, b2, b3);
        }
        __syncthreads();
        if (!half) {
            float4 pa = s_part[gl], pb = s_part[gl + 128];
            float4 oa, ob;
            oa.x = sqrtf(a0 + pa.x); oa.y = sqrtf(a1 + pa.y);
            oa.z = sqrtf(a2 + pa.z); oa.w = sqrtf(a3 + pa.w);
            ob.x = sqrtf(b0 + pb.x); ob.y = sqrtf(b1 + pb.y);
            ob.z = sqrtf(b2 + pb.z); ob.w = sqrtf(b3 + pb.w);
            ((float4*)g_intensity[sm])[g0]       = oa;
            ((float4*)g_intensity[sm])[g0 + 128] = ob;
        }
        __syncthreads();
    }

    // ============ Grid barrier (self-resetting, all CTAs co-resident) =======
    if (tid == 0) {
        __threadfence();
        atomicAdd(&g_bar_arrive, 1u);
        while (*(volatile unsigned*)&g_bar_arrive < NCTA) __nanosleep(64);
        __threadfence();
        unsigned d = atomicAdd(&g_bar_depart, 1u);
        if (d == NCTA - 1) {
            g_bar_depart = 0u;
            *(volatile unsigned*)&g_bar_arrive = 0u;
        }
    }
    __syncthreads();

    if (bid >= NMAPS * JCTAS) return;             // CTAs 128..255 done

    // ============ Phase B: region detect + compact + redux top-10 (R13) =====
    const int m = bid >> 3;
    const int j = bid & 7;
    const int b = m & 7;

    for (int i = tid; i < STG_ROWS * PADW; i += NT) rawp[i] = -CUDART_INF_F;
    __syncthreads();
    {
        const float* gi = g_intensity[m];
        for (int i = tid; i < STG_ROWS * WW; i += NT) {
            int r = i >> 7, x = i & 127;
            int grow = j * JROWS - 1 + r;
            if (grow >= 0 && grow < HH)
                rawp[r * PADW + x + 1] = __ldcg(&gi[(grow << 7) + x]);
        }
        if (tid == 0) s_cn = 0;
    }
    __syncthreads();

    for (int p = tid; p < JPIX; p += NT) {
        int yl = p >> 7, x = p & 127;
        const float* c = &rawp[(yl + 1) * PADW + (x + 1)];
        float v = c[0];
        float n0 = fmaxf(fmaxf(c[-PADW - 1], c[-PADW]), c[-PADW + 1]);
        float n1 = fmaxf(c[-1], c[1]);
        float n2 = fmaxf(fmaxf(c[PADW - 1], c[PADW]), c[PADW + 1]);
        float nmax = fmaxf(fmaxf(n0, n1), n2);
        if (v > THRESH && v >= nmax) {
            int s = atomicAdd(&s_cn, 1);          // < CAP guaranteed
            s_cval[s] = v;
            s_cidx[s] = j * JPIX + p;
        }
    }
    __syncthreads();

    if (w == 0) {
        const int n = s_cn;
        for (int k = 0; k < TOPK; k++) {
            float bv = 0.f; int bi = 0x7fffffff; int bslot = -1;
            for (int p = lane; p < n; p += 32) {
                float v = s_cval[p];
                int   i = s_cidx[p];
                if (v > 0.f && (v > bv || (v == bv && i < bi))) {
                    bv = v; bi = i; bslot = p;
                }
            }
            unsigned vb = __float_as_uint(bv);
            unsigned mx = redux_max_u32(vb);
            unsigned ic = (vb == mx) ? (unsigned)bi : 0xffffffffu;
            unsigned wi = redux_min_u32(ic);
            if (mx != 0u && vb == mx && (unsigned)bi == wi)
                s_cval[bslot] = 0.f;
            if (lane == 0) {
                g_part_val[m][j][k] = (mx != 0u) ? __uint_as_float(mx)
                                                 : -CUDART_INF_F;
                g_part_idx[m][j][k] = (mx != 0u) ? (int)wi : 0;
            }
            __syncwarp();
        }
    }
    __syncthreads();
    if (tid == 0) {
        __threadfence();
        unsigned old = atomicAdd(&g_samp_cnt[b], 1u);
        if (old == 15u) g_samp_cnt[b] = 0u;
        s_flag = (old == 15u);
    }
    __syncthreads();
    if (!s_flag) return;

    // ============ Phase C: loss for sample b (redux merges, R13) =============
    __threadfence();
    if (w < 2) {
        const int mm = (w == 0) ? b : (8 + b);
        const float* pv = &g_part_val[mm][0][0];
        const int*   pi = &g_part_idx[mm][0][0];
        for (int p = lane; p < 80; p += 32) {
            s_mv[w][p] = __ldcg(&pv[p]);
            s_mi[w][p] = __ldcg(&pi[p]);
        }
        __syncwarp();
        for (int k = 0; k < TOPK; k++) {
            float bv = 0.f; int bi = 0x7fffffff; int bslot = -1;
            #pragma unroll
            for (int q = 0; q < 3; q++) {
                int p = q * 32 + lane;
                if (p < 80) {
                    float v = s_mv[w][p];
                    int   i = s_mi[w][p];
                    if (v > 0.f && (v > bv || (v == bv && i < bi))) {
                        bv = v; bi = i; bslot = p;
                    }
                }
            }
            unsigned vb = __float_as_uint(bv);
            unsigned mx = redux_max_u32(vb);
            unsigned ic = (vb == mx) ? (unsigned)bi : 0xffffffffu;
            unsigned wi = redux_min_u32(ic);
            if (mx != 0u && vb == mx && (unsigned)bi == wi)
                s_mv[w][bslot] = 0.f;
            if (lane == 0) {
                float fv = (mx != 0u) ? __uint_as_float(mx) : -CUDART_INF_F;
                int   fi = (mx != 0u) ? (int)wi : 0;
                if (w == 0) { s_dkv[k] = fv; s_dki[k] = fi; }
                else        { s_lkv[k] = fv; s_lki[k] = fi; }
            }
            __syncwarp();
        }
    }
    __syncthreads();

    {
        const float* dbase = det + (size_t)b * CC * HW;
        const float* lbase = loc + (size_t)b * CC * HW;
        for (int idx = tid; idx < TOPK * CC; idx += NT) {
            int k = idx >> 8, c = idx & 255;
            df[k][c] = __ldg(&dbase[(size_t)c * HW + s_dki[k]]);
            lf[k][c] = __ldg(&lbase[(size_t)c * HW + s_lki[k]]);
        }
    }
    __syncthreads();

    for (int k = w; k < TOPK; k += 8) {
        float sa = 0.f, sb = 0.f;
        #pragma unroll
        for (int c = lane; c < CC; c += 32) {
            sa = fmaf(df[k][c], df[k][c], sa);
            sb = fmaf(lf[k][c], lf[k][c], sb);
        }
        #pragma unroll
        for (int o = 16; o > 0; o >>= 1) {
            sa += __shfl_down_sync(0xffffffffu, sa, o);
            sb += __shfl_down_sync(0xffffffffu, sb, o);
        }
        if (lane == 0) {
            s_na[k] = fmaxf(sqrtf(sa), EPSV);
            s_nb[k] = fmaxf(sqrtf(sb), EPSV);
        }
    }
    __syncthreads();

    float lsum = 0.f;
    for (int p = w; p < TOPK * TOPK; p += 8) {
        int i = p / TOPK, jj = p % TOPK;
        float dot = 0.f;
        #pragma unroll
        for (int c = lane; c < CC; c += 32) dot = fmaf(df[i][c], lf[jj][c], dot);
        #pragma unroll
        for (int o = 16; o > 0; o >>= 1)
            dot += __shfl_down_sync(0xffffffffu, dot, o);
        if (lane == 0 && s_dkv[i] > -CUDART_INF_F && s_lkv[jj] > -CUDART_INF_F)
            lsum += fmaxf(dot / (s_na[i] * s_nb[jj]) - MARGIN, 0.f);
    }
    if (lane == 0) s_ws[w] = lsum;
    __syncthreads();

    if (tid == 0) {
        int nd = 0, nl = 0;
        #pragma unroll
        for (int k = 0; k < TOPK; k++) {
            nd += (s_dkv[k] > -CUDART_INF_F) ? 1 : 0;
            nl += (s_lkv[k] > -CUDART_INF_F) ? 1 : 0;
        }
        float ssum = 0.f;
        #pragma unroll
        for (int q = 0; q < 8; q++) ssum += s_ws[q];
        int np = nd * nl;
        g_losses[b] = (np > 0) ? (ssum / (float)np) : 0.f;

        __threadfence();
        unsigned old = atomicAdd(&g_done_cnt, 1u);
        if (old == (BB - 1)) {
            g_done_cnt = 0u;
            __threadfence();
            float tot = 0.f;
            #pragma unroll
            for (int q = 0; q < BB; q++) tot += __ldcg(&g_losses[q]);
            out[0] = tot / (float)BB;
        }
    }
}

extern "C" void kernel_launch(void* const* d_in, const int* in_sizes, int n_in,
                              void* d_out, int out_size)
{
    const float* loc = (const float*)d_in[0];   // loc_features [8,256,128,128]
    const float* det = (const float*)d_in[1];   // det_features [8,256,128,128]
    float* out = (float*)d_out;

    fused_kernel<<<NCTA, NT>>>(det, loc, out);
}